// round 1
// baseline (speedup 1.0000x reference)
#include <cuda_runtime.h>
#include <math.h>

#define SLOPE 0.01f
#define EPS   1e-5f
#define KOFF  27

// ---------------- scratch (no allocation allowed) ----------------
// Nc = 60000 rows x 64 ch; padded capacity 65536 rows.
__device__ float g_theta[65536 * 64];
__device__ float g_phi  [65536 * 64];
__device__ float g_tmp  [65536 * 64];
__device__ float g_s1   [65536];
__device__ float g_red  [1024];   // 5 BN stat slots (sum, sumsq)

// ---------------- init: biases + zeroed stats --------------------
__global__ void init_kernel(const float* __restrict__ b_sc,
                            const float* __restrict__ b_g,
                            const float* __restrict__ b_gu,
                            const float* __restrict__ b_up,
                            float* __restrict__ out,
                            int Nc, int Nf)
{
    long t = (long)blockIdx.x * blockDim.x + threadIdx.x;
    long stride = (long)gridDim.x * blockDim.x;
    long nc64 = (long)Nc * 64;
    long nf64 = (long)Nf * 64;
    for (long i = t; i < nc64; i += stride) g_theta[i] = b_sc[i & 63];
    for (long i = t; i < nc64; i += stride) g_phi[i]   = b_g[i & 63];
    for (long i = t; i < nc64; i += stride) g_tmp[i]   = b_gu[i & 63];
    for (long i = t; i < Nc;   i += stride) g_s1[i]    = 0.f;
    for (long i = t; i < nf64; i += stride) out[i]     = b_up[i & 63];
    for (long i = t; i < 1024; i += stride) g_red[i]   = 0.f;
}

// ---------------- tiled scatter-GEMM: [E,CIN] x [CIN,64] ---------
// Block: 256 threads, tile = 64 edges x 64 channels, 4x4 register tile.
template<int CIN>
__global__ void __launch_bounds__(256)
sconv_kernel(const float* __restrict__ x,     // [*, CIN]
             const float* __restrict__ W,     // [27, CIN, 64]
             const int*   __restrict__ src,   // [27, E]
             const int*   __restrict__ dst,   // [27, E]
             int E,
             float* __restrict__ out)         // [*, 64] pre-init with bias
{
    constexpr int TE   = 64;
    constexpr int XPAD = CIN + 4;             // pad to break bank conflicts
    __shared__ float sW[CIN * 64];
    __shared__ float sx[TE * XPAD];
    __shared__ int   sdst[TE];

    const int  k  = blockIdx.y;
    const long e0 = (long)blockIdx.x * TE;

    // load W[k] (coalesced float4)
    const float4* Wk4 = (const float4*)(W + (long)k * CIN * 64);
    for (int i = threadIdx.x; i < CIN * 16; i += 256)
        ((float4*)sW)[i] = Wk4[i];

    const int* srck = src + (long)k * E;
    const int* dstk = dst + (long)k * E;

    if (threadIdx.x < TE) {
        long ge = e0 + threadIdx.x;
        sdst[threadIdx.x] = (ge < E) ? dstk[ge] : -1;
    }

    // gather x rows into smem
    {
        constexpr int TPR = CIN / 4;          // threads per row (float4 ea)
        constexpr int RPI = 256 / TPR;        // rows per iteration
        int r  = threadIdx.x / TPR;
        int cc = threadIdx.x % TPR;
        #pragma unroll
        for (int e = r; e < TE; e += RPI) {
            long ge = e0 + e;
            int  s  = (ge < E) ? srck[ge] : 0;
            float4 v = ((const float4*)(x + (long)s * CIN))[cc];
            *((float4*)(sx + e * XPAD + 4 * cc)) = v;
        }
    }
    __syncthreads();

    const int tx = threadIdx.x & 15;          // channel group: 4*tx..4*tx+3
    const int ty = threadIdx.x >> 4;          // edge group: 4*ty..4*ty+3

    float acc[4][4];
    #pragma unroll
    for (int j = 0; j < 4; j++)
        #pragma unroll
        for (int q = 0; q < 4; q++) acc[j][q] = 0.f;

    const float* sx0 = sx + (4 * ty) * XPAD;
    #pragma unroll 16
    for (int i = 0; i < CIN; i++) {
        float4 w = *((const float4*)(sW + i * 64 + 4 * tx));
        float x0 = sx0[i];
        float x1 = sx0[XPAD + i];
        float x2 = sx0[2 * XPAD + i];
        float x3 = sx0[3 * XPAD + i];
        acc[0][0] += x0 * w.x; acc[0][1] += x0 * w.y; acc[0][2] += x0 * w.z; acc[0][3] += x0 * w.w;
        acc[1][0] += x1 * w.x; acc[1][1] += x1 * w.y; acc[1][2] += x1 * w.z; acc[1][3] += x1 * w.w;
        acc[2][0] += x2 * w.x; acc[2][1] += x2 * w.y; acc[2][2] += x2 * w.z; acc[2][3] += x2 * w.w;
        acc[3][0] += x3 * w.x; acc[3][1] += x3 * w.y; acc[3][2] += x3 * w.z; acc[3][3] += x3 * w.w;
    }

    #pragma unroll
    for (int j = 0; j < 4; j++) {
        int e = 4 * ty + j;
        int d = sdst[e];
        if (d >= 0) {
            float* p = out + (long)d * 64 + 4 * tx;
            atomicAdd(p + 0, acc[j][0]);
            atomicAdd(p + 1, acc[j][1]);
            atomicAdd(p + 2, acc[j][2]);
            atomicAdd(p + 3, acc[j][3]);
        }
    }
}

// ---------------- sconv4: [E,64] x [64,1] dot-product conv -------
__global__ void __launch_bounds__(256)
sconv_dot(const float* __restrict__ x,        // [*, 64]
          const float* __restrict__ Wsum,     // [27*64]
          const int*   __restrict__ src,
          const int*   __restrict__ dst,
          int E,
          float* __restrict__ out1)           // [Nc] pre-zeroed
{
    __shared__ float sW[KOFF * 64];
    for (int i = threadIdx.x; i < KOFF * 64; i += 256) sW[i] = Wsum[i];
    __syncthreads();

    long total = (long)KOFF * E;
    int lane = threadIdx.x & 31;
    int sub  = lane >> 3;                     // 4 edges per warp
    int li   = lane & 7;                      // 8 lanes per edge
    long wg    = ((long)blockIdx.x * 256 + threadIdx.x) >> 5;
    long nwarp = ((long)gridDim.x * 256) >> 5;

    for (long w4 = wg; w4 * 4 < total; w4 += nwarp) {
        long eidx = w4 * 4 + sub;
        float v = 0.f;
        int d = -1;
        if (eidx < total) {
            int  k = (int)(eidx / E);
            long e = eidx - (long)k * E;
            int  s = src[(long)k * E + e];
            d      = dst[(long)k * E + e];
            const float4* xr = (const float4*)(x + (long)s * 64);
            float4 a  = xr[li * 2];
            float4 b2 = xr[li * 2 + 1];
            const float* wk = sW + k * 64;
            float4 wa = *(const float4*)(wk + li * 8);
            float4 wb = *(const float4*)(wk + li * 8 + 4);
            v = a.x * wa.x + a.y * wa.y + a.z * wa.z + a.w * wa.w
              + b2.x * wb.x + b2.y * wb.y + b2.z * wb.z + b2.w * wb.w;
        }
        v += __shfl_xor_sync(0xffffffffu, v, 1);
        v += __shfl_xor_sync(0xffffffffu, v, 2);
        v += __shfl_xor_sync(0xffffffffu, v, 4);
        if (li == 0 && d >= 0) atomicAdd(&out1[d], v);
    }
}

// ---------------- sconv5: [E,1] x [1,64] up conv ------------------
__global__ void __launch_bounds__(256)
sconv_up(const float* __restrict__ s1,        // [Nc]
         const float* __restrict__ Wup,       // [27*64]
         const int*   __restrict__ src,       // gather side (dst_down)
         const int*   __restrict__ dst,       // scatter side (src_down)
         int E,
         float* __restrict__ out)             // [Nf,64] pre-init b_up
{
    __shared__ float sW[KOFF * 64];
    for (int i = threadIdx.x; i < KOFF * 64; i += 256) sW[i] = Wup[i];
    __syncthreads();

    long total = (long)KOFF * E;
    int lane = threadIdx.x & 31;
    int li   = lane & 15;                     // channel group within half-warp
    long hw  = ((long)blockIdx.x * 256 + threadIdx.x) >> 4;
    long nhw = ((long)gridDim.x * 256) >> 4;

    for (long eidx = hw; eidx < total; eidx += nhw) {
        int  k = (int)(eidx / E);
        long e = eidx - (long)k * E;
        float v = s1[src[(long)k * E + e]];
        int   d = dst[(long)k * E + e];
        float4 w = *(const float4*)(sW + k * 64 + li * 4);
        float* p = out + (long)d * 64 + li * 4;
        atomicAdd(p + 0, v * w.x);
        atomicAdd(p + 1, v * w.y);
        atomicAdd(p + 2, v * w.z);
        atomicAdd(p + 3, v * w.w);
    }
}

// ---------------- BN stats: per-channel sum & sumsq ---------------
__global__ void bn_stats(const float* __restrict__ x, long n, float* __restrict__ red)
{
    __shared__ float s1[256], s2[256];
    int t = threadIdx.x;
    float a = 0.f, b = 0.f;
    for (long i = (long)blockIdx.x * 256 + t; i < n; i += (long)gridDim.x * 256) {
        float v = x[i];
        a += v; b += v * v;
    }
    s1[t] = a; s2[t] = b;
    __syncthreads();
    if (t < 64) {
        a = s1[t] + s1[t + 64] + s1[t + 128] + s1[t + 192];
        b = s2[t] + s2[t + 64] + s2[t + 128] + s2[t + 192];
        atomicAdd(&red[t], a);
        atomicAdd(&red[64 + t], b);
    }
}

// ---------------- BN apply (+leaky / +residual / sigmoid) ---------
__global__ void bn_apply(float* __restrict__ x, long nrows,
                         const float* __restrict__ gam, const float* __restrict__ bet,
                         const float* __restrict__ red,
                         const float* __restrict__ addsrc,   // may be null
                         int mode)                           // 0=leaky, 1=sigmoid
{
    long n = nrows * 64;
    float invN = 1.f / (float)nrows;
    long idx = (long)blockIdx.x * blockDim.x + threadIdx.x;
    long stride = (long)gridDim.x * blockDim.x;
    for (; idx < n; idx += stride) {
        int c = (int)(idx & 63);
        float mean  = red[c] * invN;
        float var   = red[64 + c] * invN - mean * mean;
        float scale = gam[c] * rsqrtf(var + EPS);
        float y = (x[idx] - mean) * scale + bet[c];
        if (mode == 0) {
            y = (y >= 0.f) ? y : SLOPE * y;
            if (addsrc) y += addsrc[idx];
        } else {
            y = 1.f / (1.f + expf(-y));
        }
        x[idx] = y;
    }
}

// ---------------- single-channel BN (sconv4 output) ---------------
__global__ void bn_stats1(const float* __restrict__ x, int n, float* __restrict__ red)
{
    __shared__ float s1[256], s2[256];
    float a = 0.f, b = 0.f;
    for (long i = (long)blockIdx.x * 256 + threadIdx.x; i < n; i += (long)gridDim.x * 256) {
        float v = x[i];
        a += v; b += v * v;
    }
    s1[threadIdx.x] = a; s2[threadIdx.x] = b;
    __syncthreads();
    for (int off = 128; off > 0; off >>= 1) {
        if (threadIdx.x < off) {
            s1[threadIdx.x] += s1[threadIdx.x + off];
            s2[threadIdx.x] += s2[threadIdx.x + off];
        }
        __syncthreads();
    }
    if (threadIdx.x == 0) { atomicAdd(&red[0], s1[0]); atomicAdd(&red[1], s2[0]); }
}

__global__ void bn_apply1(float* __restrict__ x, int n,
                          const float* __restrict__ gam, const float* __restrict__ bet,
                          const float* __restrict__ red)
{
    float invN = 1.f / (float)n;
    for (long i = (long)blockIdx.x * blockDim.x + threadIdx.x; i < n;
         i += (long)gridDim.x * blockDim.x) {
        float mean  = red[0] * invN;
        float var   = red[1] * invN - mean * mean;
        float scale = gam[0] * rsqrtf(var + EPS);
        float y = (x[i] - mean) * scale + bet[0];
        x[i] = (y >= 0.f) ? y : SLOPE * y;
    }
}

// ---------------- host launch --------------------------------------
extern "C" void kernel_launch(void* const* d_in, const int* in_sizes, int n_in,
                              void* d_out, int out_size)
{
    const float* gate     = (const float*)d_in[0];
    const float* shortcut = (const float*)d_in[1];
    const int*   src_down = (const int*)d_in[2];
    const int*   dst_down = (const int*)d_in[3];
    const int*   src_g    = (const int*)d_in[4];
    const int*   dst_g    = (const int*)d_in[5];
    const float* W_sc     = (const float*)d_in[6];
    const float* b_sc     = (const float*)d_in[7];
    const float* W_g      = (const float*)d_in[8];
    const float* b_g      = (const float*)d_in[9];
    const float* W_gu     = (const float*)d_in[10];
    const float* b_gu     = (const float*)d_in[11];
    const float* W_sum    = (const float*)d_in[12];
    const float* W_up     = (const float*)d_in[13];
    const float* b_up     = (const float*)d_in[14];
    const float* gam_sc   = (const float*)d_in[15];
    const float* bet_sc   = (const float*)d_in[16];
    const float* gam_g    = (const float*)d_in[17];
    const float* bet_g    = (const float*)d_in[18];
    const float* gam_gu   = (const float*)d_in[19];
    const float* bet_gu   = (const float*)d_in[20];
    const float* gam_sum  = (const float*)d_in[21];
    const float* bet_sum  = (const float*)d_in[22];
    const float* gam_up   = (const float*)d_in[23];
    const float* bet_up   = (const float*)d_in[24];

    int Nc  = in_sizes[0] / 128;
    int Nf  = in_sizes[1] / 64;
    int Ekd = in_sizes[2] / KOFF;
    int Ekg = in_sizes[4] / KOFF;
    float* out = (float*)d_out;

    float *theta, *phi, *tmp, *s1, *red;
    cudaGetSymbolAddress((void**)&theta, g_theta);
    cudaGetSymbolAddress((void**)&phi,   g_phi);
    cudaGetSymbolAddress((void**)&tmp,   g_tmp);
    cudaGetSymbolAddress((void**)&s1,    g_s1);
    cudaGetSymbolAddress((void**)&red,   g_red);

    float* red0 = red;
    float* red1 = red + 128;
    float* red2 = red + 256;
    float* red3 = red + 384;
    float* red4 = red + 512;

    // 0. init all accumulators with biases + zero stats
    init_kernel<<<2048, 256>>>(b_sc, b_g, b_gu, b_up, out, Nc, Nf);

    // 1. theta = leaky(bn(sconv(shortcut, W_sc, src_down->dst_down)))
    sconv_kernel<64><<<dim3((Ekd + 63) / 64, KOFF), 256>>>(
        shortcut, W_sc, src_down, dst_down, Ekd, theta);
    bn_stats<<<1184, 256>>>(theta, (long)Nc * 64, red0);
    bn_apply<<<1184, 256>>>(theta, Nc, gam_sc, bet_sc, red0, (const float*)0, 0);

    // 2. phi = leaky(bn(sconv(gate, W_g, src_g->dst_g)))
    sconv_kernel<128><<<dim3((Ekg + 63) / 64, KOFF), 256>>>(
        gate, W_g, src_g, dst_g, Ekg, phi);
    bn_stats<<<1184, 256>>>(phi, (long)Nc * 64, red1);
    bn_apply<<<1184, 256>>>(phi, Nc, gam_g, bet_g, red1, (const float*)0, 0);

    // 3. tmp = leaky(bn(sconv(phi, W_gu, dst_g->src_g))) + theta
    sconv_kernel<64><<<dim3((Ekg + 63) / 64, KOFF), 256>>>(
        phi, W_gu, dst_g, src_g, Ekg, tmp);
    bn_stats<<<1184, 256>>>(tmp, (long)Nc * 64, red2);
    bn_apply<<<1184, 256>>>(tmp, Nc, gam_gu, bet_gu, red2, theta, 0);

    // 4. s1 = leaky(bn(sconv(tmp, W_sum, src_g->dst_g)))  (1 channel)
    sconv_dot<<<2048, 256>>>(tmp, W_sum, src_g, dst_g, Ekg, s1);
    bn_stats1<<<592, 256>>>(s1, Nc, red3);
    bn_apply1<<<592, 256>>>(s1, Nc, gam_sum, bet_sum, red3);

    // 5. out = sigmoid(bn(sconv(s1, W_up, dst_down->src_down)))
    sconv_up<<<4096, 256>>>(s1, W_up, dst_down, src_down, Ekd, out);
    bn_stats<<<2048, 256>>>(out, (long)Nf * 64, red4);
    bn_apply<<<2048, 256>>>(out, Nf, gam_up, bet_up, red4, (const float*)0, 1);
}

// round 2
// speedup vs baseline: 1.2930x; 1.2930x over previous
#include <cuda_runtime.h>
#include <math.h>

#define SLOPE 0.01f
#define EPS   1e-5f
#define KOFF  27

// ---------------- scratch (no allocation allowed) ----------------
__device__ float g_theta[65536 * 64];
__device__ float g_phi  [65536 * 64];
__device__ float g_tmp  [65536 * 64];
__device__ float g_s1   [65536];
__device__ float g_red  [1024];   // 5 BN stat slots (sum, sumsq)

// vectorized fp32 reduction (sm_90+): 1 L2 atomic op per 4 floats
__device__ __forceinline__ void red4(float* p, float a, float b, float c, float d)
{
    asm volatile("red.global.add.v4.f32 [%0], {%1, %2, %3, %4};"
                 :: "l"(p), "f"(a), "f"(b), "f"(c), "f"(d) : "memory");
}

// ---------------- init: biases + zeroed stats --------------------
__global__ void init_kernel(const float* __restrict__ b_sc,
                            const float* __restrict__ b_g,
                            const float* __restrict__ b_gu,
                            const float* __restrict__ b_up,
                            float* __restrict__ out,
                            int Nc, int Nf)
{
    __shared__ float4 sb[4][16];
    if (threadIdx.x < 16) sb[0][threadIdx.x] = ((const float4*)b_sc)[threadIdx.x];
    else if (threadIdx.x < 32) sb[1][threadIdx.x - 16] = ((const float4*)b_g)[threadIdx.x - 16];
    else if (threadIdx.x < 48) sb[2][threadIdx.x - 32] = ((const float4*)b_gu)[threadIdx.x - 32];
    else if (threadIdx.x < 64) sb[3][threadIdx.x - 48] = ((const float4*)b_up)[threadIdx.x - 48];
    __syncthreads();

    long t = (long)blockIdx.x * blockDim.x + threadIdx.x;
    long stride = (long)gridDim.x * blockDim.x;
    long nc16 = (long)Nc * 16;   // float4 count per Nc x 64
    long nf16 = (long)Nf * 16;
    float4* th4 = (float4*)g_theta;
    float4* ph4 = (float4*)g_phi;
    float4* tm4 = (float4*)g_tmp;
    float4* ou4 = (float4*)out;
    for (long i = t; i < nc16; i += stride) th4[i] = sb[0][i & 15];
    for (long i = t; i < nc16; i += stride) ph4[i] = sb[1][i & 15];
    for (long i = t; i < nc16; i += stride) tm4[i] = sb[2][i & 15];
    for (long i = t; i < nf16; i += stride) ou4[i] = sb[3][i & 15];
    for (long i = t; i < Nc;   i += stride) g_s1[i] = 0.f;
    for (long i = t; i < 1024; i += stride) g_red[i] = 0.f;
}

// ---------------- tiled scatter-GEMM: [E,CIN] x [CIN,64] ---------
template<int CIN>
__global__ void __launch_bounds__(256)
sconv_kernel(const float* __restrict__ x,     // [*, CIN]
             const float* __restrict__ W,     // [27, CIN, 64]
             const int*   __restrict__ src,   // [27, E]
             const int*   __restrict__ dst,   // [27, E]
             int E,
             float* __restrict__ out)         // [*, 64] pre-init with bias
{
    constexpr int TE   = 64;
    constexpr int XPAD = CIN + 4;
    __shared__ float sW[CIN * 64];
    __shared__ float sx[TE * XPAD];
    __shared__ int   sdst[TE];

    const int  k  = blockIdx.y;
    const long e0 = (long)blockIdx.x * TE;

    const float4* Wk4 = (const float4*)(W + (long)k * CIN * 64);
    for (int i = threadIdx.x; i < CIN * 16; i += 256)
        ((float4*)sW)[i] = Wk4[i];

    const int* srck = src + (long)k * E;
    const int* dstk = dst + (long)k * E;

    if (threadIdx.x < TE) {
        long ge = e0 + threadIdx.x;
        sdst[threadIdx.x] = (ge < E) ? dstk[ge] : -1;
    }

    {
        constexpr int TPR = CIN / 4;
        constexpr int RPI = 256 / TPR;
        int r  = threadIdx.x / TPR;
        int cc = threadIdx.x % TPR;
        #pragma unroll
        for (int e = r; e < TE; e += RPI) {
            long ge = e0 + e;
            int  s  = (ge < E) ? srck[ge] : 0;
            float4 v = ((const float4*)(x + (long)s * CIN))[cc];
            *((float4*)(sx + e * XPAD + 4 * cc)) = v;
        }
    }
    __syncthreads();

    const int tx = threadIdx.x & 15;
    const int ty = threadIdx.x >> 4;

    float acc[4][4];
    #pragma unroll
    for (int j = 0; j < 4; j++)
        #pragma unroll
        for (int q = 0; q < 4; q++) acc[j][q] = 0.f;

    const float* sx0 = sx + (4 * ty) * XPAD;
    #pragma unroll 16
    for (int i = 0; i < CIN; i++) {
        float4 w = *((const float4*)(sW + i * 64 + 4 * tx));
        float x0 = sx0[i];
        float x1 = sx0[XPAD + i];
        float x2 = sx0[2 * XPAD + i];
        float x3 = sx0[3 * XPAD + i];
        acc[0][0] += x0 * w.x; acc[0][1] += x0 * w.y; acc[0][2] += x0 * w.z; acc[0][3] += x0 * w.w;
        acc[1][0] += x1 * w.x; acc[1][1] += x1 * w.y; acc[1][2] += x1 * w.z; acc[1][3] += x1 * w.w;
        acc[2][0] += x2 * w.x; acc[2][1] += x2 * w.y; acc[2][2] += x2 * w.z; acc[2][3] += x2 * w.w;
        acc[3][0] += x3 * w.x; acc[3][1] += x3 * w.y; acc[3][2] += x3 * w.z; acc[3][3] += x3 * w.w;
    }

    #pragma unroll
    for (int j = 0; j < 4; j++) {
        int d = sdst[4 * ty + j];
        if (d >= 0) {
            float* p = out + (long)d * 64 + 4 * tx;
            red4(p, acc[j][0], acc[j][1], acc[j][2], acc[j][3]);
        }
    }
}

// ---------------- sconv4: [E,64] x [64,1] dot-product conv -------
__global__ void __launch_bounds__(256)
sconv_dot(const float* __restrict__ x,
          const float* __restrict__ Wsum,
          const int*   __restrict__ src,
          const int*   __restrict__ dst,
          int E,
          float* __restrict__ out1)
{
    __shared__ float sW[KOFF * 64];
    for (int i = threadIdx.x; i < KOFF * 64; i += 256) sW[i] = Wsum[i];
    __syncthreads();

    long total = (long)KOFF * E;
    int lane = threadIdx.x & 31;
    int sub  = lane >> 3;
    int li   = lane & 7;
    long wg    = ((long)blockIdx.x * 256 + threadIdx.x) >> 5;
    long nwarp = ((long)gridDim.x * 256) >> 5;

    for (long w4 = wg; w4 * 4 < total; w4 += nwarp) {
        long eidx = w4 * 4 + sub;
        float v = 0.f;
        int d = -1;
        if (eidx < total) {
            int  k = (int)(eidx / E);
            long e = eidx - (long)k * E;
            int  s = src[(long)k * E + e];
            d      = dst[(long)k * E + e];
            const float4* xr = (const float4*)(x + (long)s * 64);
            float4 a  = xr[li * 2];
            float4 b2 = xr[li * 2 + 1];
            const float* wk = sW + k * 64;
            float4 wa = *(const float4*)(wk + li * 8);
            float4 wb = *(const float4*)(wk + li * 8 + 4);
            v = a.x * wa.x + a.y * wa.y + a.z * wa.z + a.w * wa.w
              + b2.x * wb.x + b2.y * wb.y + b2.z * wb.z + b2.w * wb.w;
        }
        v += __shfl_xor_sync(0xffffffffu, v, 1);
        v += __shfl_xor_sync(0xffffffffu, v, 2);
        v += __shfl_xor_sync(0xffffffffu, v, 4);
        if (li == 0 && d >= 0) atomicAdd(&out1[d], v);
    }
}

// ---------------- sconv5: [E,1] x [1,64] up conv ------------------
__global__ void __launch_bounds__(256)
sconv_up(const float* __restrict__ s1,
         const float* __restrict__ Wup,
         const int*   __restrict__ src,
         const int*   __restrict__ dst,
         int E,
         float* __restrict__ out)
{
    __shared__ float sW[KOFF * 64];
    for (int i = threadIdx.x; i < KOFF * 64; i += 256) sW[i] = Wup[i];
    __syncthreads();

    long total = (long)KOFF * E;
    int lane = threadIdx.x & 31;
    int li   = lane & 15;
    long hw  = ((long)blockIdx.x * 256 + threadIdx.x) >> 4;
    long nhw = ((long)gridDim.x * 256) >> 4;

    for (long eidx = hw; eidx < total; eidx += nhw) {
        int  k = (int)(eidx / E);
        long e = eidx - (long)k * E;
        float v = s1[src[(long)k * E + e]];
        int   d = dst[(long)k * E + e];
        float4 w = *(const float4*)(sW + k * 64 + li * 4);
        float* p = out + (long)d * 64 + li * 4;
        red4(p, v * w.x, v * w.y, v * w.z, v * w.w);
    }
}

// ---------------- BN stats: per-channel sum & sumsq (float4) ------
__global__ void bn_stats(const float* __restrict__ x, long nrows, float* __restrict__ red)
{
    // each thread owns a fixed channel quad: q = global_f4_idx & 15
    __shared__ float s1[256 * 4], s2[256 * 4];
    int t = threadIdx.x;
    long n4 = nrows * 16;
    float a0=0,a1=0,a2=0,a3=0, b0=0,b1=0,b2=0,b3=0;
    const float4* x4 = (const float4*)x;
    for (long i = (long)blockIdx.x * 256 + t; i < n4; i += (long)gridDim.x * 256) {
        float4 v = x4[i];
        a0 += v.x; b0 += v.x * v.x;
        a1 += v.y; b1 += v.y * v.y;
        a2 += v.z; b2 += v.z * v.z;
        a3 += v.w; b3 += v.w * v.w;
    }
    s1[t*4+0]=a0; s1[t*4+1]=a1; s1[t*4+2]=a2; s1[t*4+3]=a3;
    s2[t*4+0]=b0; s2[t*4+1]=b1; s2[t*4+2]=b2; s2[t*4+3]=b3;
    __syncthreads();
    // channel of (thread t, comp c) = 4*(t&15)+c.  Reduce the 16 threads
    // sharing each quad. Threads t<64: quad q=t>>2, comp=t&3.
    if (t < 64) {
        int q = t >> 2, comp = t & 3;
        float sa = 0.f, sb = 0.f;
        #pragma unroll
        for (int j = 0; j < 16; j++) {
            sa += s1[(j * 16 + q) * 4 + comp];
            sb += s2[(j * 16 + q) * 4 + comp];
        }
        atomicAdd(&red[4 * q + comp], sa);
        atomicAdd(&red[64 + 4 * q + comp], sb);
    }
}

// ---------------- BN apply (+leaky / +residual / sigmoid), float4 -
__global__ void bn_apply(float* __restrict__ x, long nrows,
                         const float* __restrict__ gam, const float* __restrict__ bet,
                         const float* __restrict__ red,
                         const float* __restrict__ addsrc,
                         int mode)
{
    __shared__ float sm[64], ss[64], sbt[64];
    if (threadIdx.x < 64) {
        int c = threadIdx.x;
        float invN  = 1.f / (float)nrows;
        float mean  = red[c] * invN;
        float var   = red[64 + c] * invN - mean * mean;
        float scale = gam[c] * rsqrtf(var + EPS);
        sm[c] = mean; ss[c] = scale; sbt[c] = bet[c];
    }
    __syncthreads();

    long n4 = nrows * 16;
    float4* x4 = (float4*)x;
    const float4* a4 = (const float4*)addsrc;
    long idx = (long)blockIdx.x * blockDim.x + threadIdx.x;
    long stride = (long)gridDim.x * blockDim.x;
    for (; idx < n4; idx += stride) {
        int c = (int)(idx & 15) * 4;
        float4 v = x4[idx];
        float y0 = (v.x - sm[c+0]) * ss[c+0] + sbt[c+0];
        float y1 = (v.y - sm[c+1]) * ss[c+1] + sbt[c+1];
        float y2 = (v.z - sm[c+2]) * ss[c+2] + sbt[c+2];
        float y3 = (v.w - sm[c+3]) * ss[c+3] + sbt[c+3];
        if (mode == 0) {
            y0 = (y0 >= 0.f) ? y0 : SLOPE * y0;
            y1 = (y1 >= 0.f) ? y1 : SLOPE * y1;
            y2 = (y2 >= 0.f) ? y2 : SLOPE * y2;
            y3 = (y3 >= 0.f) ? y3 : SLOPE * y3;
            if (addsrc) {
                float4 a = a4[idx];
                y0 += a.x; y1 += a.y; y2 += a.z; y3 += a.w;
            }
        } else {
            y0 = 1.f / (1.f + expf(-y0));
            y1 = 1.f / (1.f + expf(-y1));
            y2 = 1.f / (1.f + expf(-y2));
            y3 = 1.f / (1.f + expf(-y3));
        }
        x4[idx] = make_float4(y0, y1, y2, y3);
    }
}

// ---------------- single-channel BN (sconv4 output) ---------------
__global__ void bn_stats1(const float* __restrict__ x, int n, float* __restrict__ red)
{
    __shared__ float s1[256], s2[256];
    float a = 0.f, b = 0.f;
    for (long i = (long)blockIdx.x * 256 + threadIdx.x; i < n; i += (long)gridDim.x * 256) {
        float v = x[i];
        a += v; b += v * v;
    }
    s1[threadIdx.x] = a; s2[threadIdx.x] = b;
    __syncthreads();
    for (int off = 128; off > 0; off >>= 1) {
        if (threadIdx.x < off) {
            s1[threadIdx.x] += s1[threadIdx.x + off];
            s2[threadIdx.x] += s2[threadIdx.x + off];
        }
        __syncthreads();
    }
    if (threadIdx.x == 0) { atomicAdd(&red[0], s1[0]); atomicAdd(&red[1], s2[0]); }
}

__global__ void bn_apply1(float* __restrict__ x, int n,
                          const float* __restrict__ gam, const float* __restrict__ bet,
                          const float* __restrict__ red)
{
    float invN = 1.f / (float)n;
    for (long i = (long)blockIdx.x * blockDim.x + threadIdx.x; i < n;
         i += (long)gridDim.x * blockDim.x) {
        float mean  = red[0] * invN;
        float var   = red[1] * invN - mean * mean;
        float scale = gam[0] * rsqrtf(var + EPS);
        float y = (x[i] - mean) * scale + bet[0];
        x[i] = (y >= 0.f) ? y : SLOPE * y;
    }
}

// ---------------- host launch --------------------------------------
extern "C" void kernel_launch(void* const* d_in, const int* in_sizes, int n_in,
                              void* d_out, int out_size)
{
    const float* gate     = (const float*)d_in[0];
    const float* shortcut = (const float*)d_in[1];
    const int*   src_down = (const int*)d_in[2];
    const int*   dst_down = (const int*)d_in[3];
    const int*   src_g    = (const int*)d_in[4];
    const int*   dst_g    = (const int*)d_in[5];
    const float* W_sc     = (const float*)d_in[6];
    const float* b_sc     = (const float*)d_in[7];
    const float* W_g      = (const float*)d_in[8];
    const float* b_g      = (const float*)d_in[9];
    const float* W_gu     = (const float*)d_in[10];
    const float* b_gu     = (const float*)d_in[11];
    const float* W_sum    = (const float*)d_in[12];
    const float* W_up     = (const float*)d_in[13];
    const float* b_up     = (const float*)d_in[14];
    const float* gam_sc   = (const float*)d_in[15];
    const float* bet_sc   = (const float*)d_in[16];
    const float* gam_g    = (const float*)d_in[17];
    const float* bet_g    = (const float*)d_in[18];
    const float* gam_gu   = (const float*)d_in[19];
    const float* bet_gu   = (const float*)d_in[20];
    const float* gam_sum  = (const float*)d_in[21];
    const float* bet_sum  = (const float*)d_in[22];
    const float* gam_up   = (const float*)d_in[23];
    const float* bet_up   = (const float*)d_in[24];

    int Nc  = in_sizes[0] / 128;
    int Nf  = in_sizes[1] / 64;
    int Ekd = in_sizes[2] / KOFF;
    int Ekg = in_sizes[4] / KOFF;
    float* out = (float*)d_out;

    float *theta, *phi, *tmp, *s1, *red;
    cudaGetSymbolAddress((void**)&theta, g_theta);
    cudaGetSymbolAddress((void**)&phi,   g_phi);
    cudaGetSymbolAddress((void**)&tmp,   g_tmp);
    cudaGetSymbolAddress((void**)&s1,    g_s1);
    cudaGetSymbolAddress((void**)&red,   g_red);

    float* red0 = red;
    float* red1 = red + 128;
    float* red2 = red + 256;
    float* red3 = red + 384;
    float* red4p = red + 512;

    init_kernel<<<1184, 256>>>(b_sc, b_g, b_gu, b_up, out, Nc, Nf);

    // 1. theta = leaky(bn(sconv(shortcut, W_sc, src_down->dst_down)))
    sconv_kernel<64><<<dim3((Ekd + 63) / 64, KOFF), 256>>>(
        shortcut, W_sc, src_down, dst_down, Ekd, theta);
    bn_stats<<<592, 256>>>(theta, Nc, red0);
    bn_apply<<<592, 256>>>(theta, Nc, gam_sc, bet_sc, red0, (const float*)0, 0);

    // 2. phi = leaky(bn(sconv(gate, W_g, src_g->dst_g)))
    sconv_kernel<128><<<dim3((Ekg + 63) / 64, KOFF), 256>>>(
        gate, W_g, src_g, dst_g, Ekg, phi);
    bn_stats<<<592, 256>>>(phi, Nc, red1);
    bn_apply<<<592, 256>>>(phi, Nc, gam_g, bet_g, red1, (const float*)0, 0);

    // 3. tmp = leaky(bn(sconv(phi, W_gu, dst_g->src_g))) + theta
    sconv_kernel<64><<<dim3((Ekg + 63) / 64, KOFF), 256>>>(
        phi, W_gu, dst_g, src_g, Ekg, tmp);
    bn_stats<<<592, 256>>>(tmp, Nc, red2);
    bn_apply<<<592, 256>>>(tmp, Nc, gam_gu, bet_gu, red2, theta, 0);

    // 4. s1 = leaky(bn(sconv(tmp, W_sum, src_g->dst_g)))  (1 channel)
    sconv_dot<<<1184, 256>>>(tmp, W_sum, src_g, dst_g, Ekg, s1);
    bn_stats1<<<592, 256>>>(s1, Nc, red3);
    bn_apply1<<<592, 256>>>(s1, Nc, gam_sum, bet_sum, red3);

    // 5. out = sigmoid(bn(sconv(s1, W_up, dst_down->src_down)))
    sconv_up<<<2368, 256>>>(s1, W_up, dst_down, src_down, Ekd, out);
    bn_stats<<<1184, 256>>>(out, Nf, red4p);
    bn_apply<<<1184, 256>>>(out, Nf, gam_up, bet_up, red4p, (const float*)0, 1);
}